// round 15
// baseline (speedup 1.0000x reference)
#include <cuda_runtime.h>
#include <cstdint>

// Shapes: x (2048,128,32), clusters (32,128,32), out (2048,32)
#define N_TOTAL 2048
#define T_DIM   128
#define F_DIM   32
#define K_DIM   32
#define THREADS 256
#define TCH     16            // t per chunk = one k16 MMA step
#define NCH     8
#define NROWS   64            // n rows per block
#define NTILES  (N_TOTAL / NROWS)   // 32
#define FGROUPS 8

// smem byte offsets (main phase)
#define OFF_XNAT 0
#define XNAT_SZ  16384        // [64 n][16 t] x float4 (4 f's), per slot
#define OFF_CNAT 32768
#define CNAT_SZ  8192         // [32 k][16 t] x float4, per slot
#define OFF_AH   49152        // 4 planes x [64][8] u32 (bf16x2 t-pairs), 2048B each
#define OFF_AL   57344
#define OFF_BH   65536        // 4 planes x [32][8] u32, 1024B each
#define OFF_BL   69632
#define SMEM_TOTAL 73728      // 72KB -> 2 CTAs/SM
// epilogue overlays (main-phase buffers dead)
#define OFF_X2RED 0           // [512][4] f32
#define OFF_C2RED 8192        // [256][4] f32
#define OFF_X2S   12288       // [4][64] f32
#define OFF_C2S   13312       // [4][32] f32
#define OFF_EDS   16384       // [4][64][32] f32 (32KB)

__device__ float g_part[N_TOTAL * FGROUPS * K_DIM];   // [n][fg][k] — 2MB

__device__ __forceinline__ void cp_async16(uint32_t dst, const void* src) {
    asm volatile("cp.async.cg.shared.global [%0], [%1], 16;\n" :: "r"(dst), "l"(src));
}
__device__ __forceinline__ void cp_commit() {
    asm volatile("cp.async.commit_group;\n" ::: "memory");
}
__device__ __forceinline__ void cp_wait1() {
    asm volatile("cp.async.wait_group 1;\n" ::: "memory");
}
__device__ __forceinline__ float fsqrt_approx(float v) {
    float r; asm("sqrt.approx.f32 %0, %1;" : "=f"(r) : "f"(v)); return r;
}
__device__ __forceinline__ float frcp_approx(float v) {
    float r; asm("rcp.approx.f32 %0, %1;" : "=f"(r) : "f"(v)); return r;
}
__device__ __forceinline__ uint32_t pack_bf16(float a, float b) {
    uint32_t r; asm("cvt.rn.bf16x2.f32 %0, %1, %2;" : "=r"(r) : "f"(b), "f"(a)); return r;
}
__device__ __forceinline__ void mma_bf16(float* d, const uint32_t* a, const uint32_t* b) {
    asm volatile("mma.sync.aligned.m16n8k16.row.col.f32.bf16.bf16.f32 "
        "{%0,%1,%2,%3}, {%4,%5,%6,%7}, {%8,%9}, {%0,%1,%2,%3};"
        : "+f"(d[0]), "+f"(d[1]), "+f"(d[2]), "+f"(d[3])
        : "r"(a[0]), "r"(a[1]), "r"(a[2]), "r"(a[3]), "r"(b[0]), "r"(b[1]));
}
__device__ __forceinline__ void split_pair(float v0, float v1, uint32_t& hi, uint32_t& lo,
                                           float& sq) {
    hi = pack_bf16(v0, v1);
    float h0 = __uint_as_float(hi << 16);
    float h1 = __uint_as_float(hi & 0xFFFF0000u);
    lo = pack_bf16(v0 - h0, v1 - h1);
    sq = fmaf(v0, v0, fmaf(v1, v1, sq));
}

// ================= Kernel 1: bf16-split HMMA partial distances ================
extern "C" __global__ void __launch_bounds__(THREADS, 2)
ts_mma_kernel(const float* __restrict__ x, const float* __restrict__ clusters) {
    extern __shared__ char smem[];
    const uint32_t sb = (uint32_t)__cvta_generic_to_shared(smem);

    const int tid  = threadIdx.x;
    const int lane = tid & 31;
    const int w    = tid >> 5;
    const int fg   = blockIdx.x & 7;             // f-group (4 f's)
    const int n0   = (blockIdx.x >> 3) * NROWS;  // n-tile base
    const int f    = w >> 1;                     // warp's f plane (0..3)
    const int mh   = w & 1;                      // m-half (32 rows)
    const int g    = lane >> 2;                  // groupID
    const int t4   = lane & 3;                   // threadID in group

    // ---- cp.async natural-tile addressing ------------------------------------
    // x cells: idx = tid + 256r (r<4): n = (tid>>4)+16r, t = tid&15
    const char* xsrc = (const char*)x
        + ((size_t)(n0 + (tid >> 4)) * T_DIM + (tid & 15)) * (F_DIM * 4) + (size_t)fg * 16;
    const char* csrc = (const char*)clusters
        + ((size_t)(tid >> 4) * T_DIM + (tid & 15)) * (F_DIM * 4) + (size_t)fg * 16;
    const uint32_t xdst = sb + OFF_XNAT + (uint32_t)tid * 16;
    const uint32_t cdst = sb + OFF_CNAT + (uint32_t)tid * 16;

    auto prefetch = [&](int ci) {
        if (ci >= NCH) return;
        const size_t tadv = (size_t)ci * TCH * (F_DIM * 4);       // 2048B per chunk
        const uint32_t xo = (uint32_t)(ci & 1) * XNAT_SZ;
        const uint32_t co = (uint32_t)(ci & 1) * CNAT_SZ;
        #pragma unroll
        for (int r = 0; r < 4; r++)     // 1024 x-cells
            cp_async16(xdst + xo + (uint32_t)(r * 4096), xsrc + tadv + (size_t)r * 262144);
        #pragma unroll
        for (int r = 0; r < 2; r++)     // 512 c-cells
            cp_async16(cdst + co + (uint32_t)(r * 4096), csrc + tadv + (size_t)r * 262144);
    };

    // ---- accumulators --------------------------------------------------------
    float acc[2][4][4];                 // [m-tile][n-tile][frag]
    #pragma unroll
    for (int mt = 0; mt < 2; mt++)
        #pragma unroll
        for (int nt = 0; nt < 4; nt++)
            #pragma unroll
            for (int e = 0; e < 4; e++) acc[mt][nt][e] = 0.f;
    float x2pr[2][4], c2pr[4];
    #pragma unroll
    for (int r = 0; r < 2; r++)
        #pragma unroll
        for (int ff = 0; ff < 4; ff++) x2pr[r][ff] = 0.f;
    #pragma unroll
    for (int ff = 0; ff < 4; ff++) c2pr[ff] = 0.f;

    prefetch(0); cp_commit();

    for (int ci = 0; ci < NCH; ci++) {
        prefetch(ci + 1); cp_commit();   // uniform group count (empty tail)
        cp_wait1();
        __syncthreads();                  // natural ci visible; planes free

        const float4* xn = (const float4*)(smem + OFF_XNAT + (ci & 1) * XNAT_SZ);
        const float4* cn = (const float4*)(smem + OFF_CNAT + (ci & 1) * CNAT_SZ);

        // ---- transpose + split: x -> A planes, accumulate x^2 ----------------
        #pragma unroll
        for (int r = 0; r < 2; r++) {
            const int cell = tid + 256 * r;     // 512 cells: n = cell>>3, tp = cell&7
            const int n  = cell >> 3;
            const int tp = cell & 7;
            float4 v0 = xn[n * 16 + 2 * tp];
            float4 v1 = xn[n * 16 + 2 * tp + 1];
            uint32_t hi, lo;
            uint32_t* AH0 = (uint32_t*)(smem + OFF_AH) + n * 8 + tp;
            uint32_t* AL0 = (uint32_t*)(smem + OFF_AL) + n * 8 + tp;
            split_pair(v0.x, v1.x, hi, lo, x2pr[r][0]); AH0[0*512] = hi; AL0[0*512] = lo;
            split_pair(v0.y, v1.y, hi, lo, x2pr[r][1]); AH0[1*512] = hi; AL0[1*512] = lo;
            split_pair(v0.z, v1.z, hi, lo, x2pr[r][2]); AH0[2*512] = hi; AL0[2*512] = lo;
            split_pair(v0.w, v1.w, hi, lo, x2pr[r][3]); AH0[3*512] = hi; AL0[3*512] = lo;
        }
        // ---- transpose + split: c -> B planes --------------------------------
        {
            const int k  = tid >> 3;
            const int tp = tid & 7;
            float4 v0 = cn[k * 16 + 2 * tp];
            float4 v1 = cn[k * 16 + 2 * tp + 1];
            uint32_t hi, lo;
            uint32_t* BH0 = (uint32_t*)(smem + OFF_BH) + k * 8 + tp;
            uint32_t* BL0 = (uint32_t*)(smem + OFF_BL) + k * 8 + tp;
            split_pair(v0.x, v1.x, hi, lo, c2pr[0]); BH0[0*256] = hi; BL0[0*256] = lo;
            split_pair(v0.y, v1.y, hi, lo, c2pr[1]); BH0[1*256] = hi; BL0[1*256] = lo;
            split_pair(v0.z, v1.z, hi, lo, c2pr[2]); BH0[2*256] = hi; BL0[2*256] = lo;
            split_pair(v0.w, v1.w, hi, lo, c2pr[3]); BH0[3*256] = hi; BL0[3*256] = lo;
        }
        __syncthreads();                 // planes written

        // ---- warp MMAs: 2 m-tiles x 4 n-tiles x 3 split terms ----------------
        {
            const uint32_t* AH = (const uint32_t*)(smem + OFF_AH) + f * 512;
            const uint32_t* AL = (const uint32_t*)(smem + OFF_AL) + f * 512;
            const uint32_t* BH = (const uint32_t*)(smem + OFF_BH) + f * 256;
            const uint32_t* BL = (const uint32_t*)(smem + OFF_BL) + f * 256;

            uint32_t bh[4][2], bl[4][2];
            #pragma unroll
            for (int nt = 0; nt < 4; nt++) {
                int row = nt * 8 + g;
                bh[nt][0] = BH[row * 8 + t4];  bh[nt][1] = BH[row * 8 + t4 + 4];
                bl[nt][0] = BL[row * 8 + t4];  bl[nt][1] = BL[row * 8 + t4 + 4];
            }
            #pragma unroll
            for (int mt = 0; mt < 2; mt++) {
                int r0 = mh * 32 + mt * 16 + g;
                uint32_t ah[4], al[4];
                ah[0] = AH[r0 * 8 + t4];       ah[1] = AH[(r0 + 8) * 8 + t4];
                ah[2] = AH[r0 * 8 + t4 + 4];   ah[3] = AH[(r0 + 8) * 8 + t4 + 4];
                al[0] = AL[r0 * 8 + t4];       al[1] = AL[(r0 + 8) * 8 + t4];
                al[2] = AL[r0 * 8 + t4 + 4];   al[3] = AL[(r0 + 8) * 8 + t4 + 4];
                #pragma unroll
                for (int nt = 0; nt < 4; nt++) {
                    mma_bf16(acc[mt][nt], ah, bh[nt]);   // hi*hi
                    mma_bf16(acc[mt][nt], al, bh[nt]);   // lo*hi
                    mma_bf16(acc[mt][nt], ah, bl[nt]);   // hi*lo
                }
            }
        }
        __syncthreads();                 // MMAs done -> planes free for next chunk
    }

    // ---- epilogue: reduce x2/c2, sqrt per f, reduce f, write global ----------
    float* x2red = (float*)(smem + OFF_X2RED);
    float* c2red = (float*)(smem + OFF_C2RED);
    float* x2s   = (float*)(smem + OFF_X2S);
    float* c2s   = (float*)(smem + OFF_C2S);
    float* eds   = (float*)(smem + OFF_EDS);

    #pragma unroll
    for (int r = 0; r < 2; r++)
        #pragma unroll
        for (int ff = 0; ff < 4; ff++)
            x2red[(tid + 256 * r) * 4 + ff] = x2pr[r][ff];
    #pragma unroll
    for (int ff = 0; ff < 4; ff++) c2red[tid * 4 + ff] = c2pr[ff];
    __syncthreads();

    if (tid < 64) {                      // x2s[f][n]
        #pragma unroll
        for (int ff = 0; ff < 4; ff++) {
            float s = 0.f;
            #pragma unroll
            for (int j = 0; j < 8; j++) s += x2red[(tid * 8 + j) * 4 + ff];
            x2s[ff * 64 + tid] = s;
        }
    } else if (tid < 96) {               // c2s[f][k]
        int k = tid - 64;
        #pragma unroll
        for (int ff = 0; ff < 4; ff++) {
            float s = 0.f;
            #pragma unroll
            for (int j = 0; j < 8; j++) s += c2red[(k * 8 + j) * 4 + ff];
            c2s[ff * 32 + k] = s;
        }
    }
    __syncthreads();

    // sqrt pass: thread's D fragments -> eds[f][row][k]
    {
        const float* x2f = x2s + f * 64;
        const float* c2f = c2s + f * 32;
        float* ef = eds + f * 2048;
        #pragma unroll
        for (int mt = 0; mt < 2; mt++) {
            int r0 = mh * 32 + mt * 16 + g, r1 = r0 + 8;
            float xa = x2f[r0], xb = x2f[r1];
            #pragma unroll
            for (int nt = 0; nt < 4; nt++) {
                int k0 = nt * 8 + t4 * 2, k1 = k0 + 1;
                float ca = c2f[k0], cb = c2f[k1];
                ef[r0 * 32 + k0] = fsqrt_approx(fmaxf(fmaf(-2.f, acc[mt][nt][0], xa + ca), 0.f));
                ef[r0 * 32 + k1] = fsqrt_approx(fmaxf(fmaf(-2.f, acc[mt][nt][1], xa + cb), 0.f));
                ef[r1 * 32 + k0] = fsqrt_approx(fmaxf(fmaf(-2.f, acc[mt][nt][2], xb + ca), 0.f));
                ef[r1 * 32 + k1] = fsqrt_approx(fmaxf(fmaf(-2.f, acc[mt][nt][3], xb + cb), 0.f));
            }
        }
    }
    __syncthreads();

    // f-sum -> g_part[n][fg][k] (coalesced 128B per (n,fg))
    #pragma unroll
    for (int i = 0; i < 8; i++) {        // 2048 (n,k) pairs
        int p = tid + 256 * i;
        int n = p >> 5, k = p & 31;
        float tot = eds[0 * 2048 + p] + eds[1 * 2048 + p]
                  + eds[2 * 2048 + p] + eds[3 * 2048 + p];
        g_part[(((size_t)(n0 + n)) * FGROUPS + fg) * K_DIM + k] = tot;
    }
}

// ================= Kernel 2: reduce f-groups + Student-t ======================
extern "C" __global__ void __launch_bounds__(256, 1)
ts_softassign_kernel(float* __restrict__ out) {
    const int w    = threadIdx.x >> 5;
    const int lane = threadIdx.x & 31;           // = k
    const int nb   = blockIdx.x * 32 + w * 4;    // 64 blocks x 8 warps x 4 n

    #pragma unroll
    for (int i = 0; i < 4; i++) {
        const int n = nb + i;
        float d = 0.f;
        #pragma unroll
        for (int fgi = 0; fgi < FGROUPS; fgi++)   // coalesced: consecutive 128B lines
            d += g_part[((size_t)n * FGROUPS + fgi) * K_DIM + lane];
        float q = frcp_approx(fmaf(d, d, 1.0f));  // alpha = 1
        float s = q;
        #pragma unroll
        for (int off = 16; off > 0; off >>= 1)
            s += __shfl_xor_sync(0xffffffffu, s, off);
        out[(size_t)n * K_DIM + lane] = q * frcp_approx(s);
    }
}

extern "C" void kernel_launch(void* const* d_in, const int* in_sizes, int n_in,
                              void* d_out, int out_size) {
    const float* x        = (const float*)d_in[0];   // (2048, 128, 32)
    const float* clusters = (const float*)d_in[1];   // (32, 128, 32)
    float* out            = (float*)d_out;           // (2048, 32)
    (void)in_sizes; (void)n_in; (void)out_size;

    cudaFuncSetAttribute(ts_mma_kernel,
                         cudaFuncAttributeMaxDynamicSharedMemorySize, SMEM_TOTAL);
    ts_mma_kernel<<<NTILES * FGROUPS, THREADS, SMEM_TOTAL>>>(x, clusters);
    ts_softassign_kernel<<<N_TOTAL / 32, 256>>>(out);
}

// round 16
// speedup vs baseline: 1.4904x; 1.4904x over previous
#include <cuda_runtime.h>
#include <cstdint>

// Shapes: x (2048,128,32), clusters (32,128,32), out (2048,32)
#define N_TOTAL 2048
#define T_DIM   128
#define F_DIM   32
#define K_DIM   32
#define THREADS 512           // 16 warps = 4/SMSP
#define TCH     8             // t per chunk = one k8 tf32 MMA step
#define NCH     16
#define NROWS   16            // n rows per CTA
#define NBLOCKS (N_TOTAL / NROWS)   // 128

// ---- smem layout (bytes) ----
#define OFF_XNAT  0
#define XNAT_SZ   16384       // [16 n][8 t][8 fc] 16B cells, per slot
#define OFF_CNAT  32768
#define CNAT_SZ   32768       // [32 k][8 t][8 fc] cells, per slot
#define OFF_APL   98304       // A planes: 32 f x 132 words (pad 4) = 16896 B
#define A_STRIDE  132
#define OFF_BPL   115200      // B planes: 32 f x 260 words (pad 4) = 33280 B
#define B_STRIDE  260
#define SMEM_TOTAL 148480
// epilogue overlays (main buffers dead)
#define OFF_X2RED 0           // [2 q][16 n][32 f] = 4KB
#define OFF_C2RED 4096        // [2 q][32 k][32 f] = 8KB
#define OFF_X2S   12288       // [16 n][32 f] = 2KB
#define OFF_C2S   14336       // [32 k][32 f] = 4KB
#define OFF_EPART 32768       // [16 w][16 n][32 k] = 32KB

__device__ __forceinline__ void cp_async16(uint32_t dst, const void* src) {
    asm volatile("cp.async.cg.shared.global [%0], [%1], 16;\n" :: "r"(dst), "l"(src));
}
__device__ __forceinline__ void cp_commit() {
    asm volatile("cp.async.commit_group;\n" ::: "memory");
}
__device__ __forceinline__ void cp_wait1() {
    asm volatile("cp.async.wait_group 1;\n" ::: "memory");
}
__device__ __forceinline__ float fsqrt_approx(float v) {
    float r; asm("sqrt.approx.f32 %0, %1;" : "=f"(r) : "f"(v)); return r;
}
__device__ __forceinline__ float frcp_approx(float v) {
    float r; asm("rcp.approx.f32 %0, %1;" : "=f"(r) : "f"(v)); return r;
}
__device__ __forceinline__ uint32_t cvt_tf32(float v) {
    uint32_t r; asm("cvt.rna.tf32.f32 %0, %1;" : "=r"(r) : "f"(v)); return r;
}
// m16n8k8 tf32 MMA — fragment layout experimentally validated in R13 (bf16 twin)
__device__ __forceinline__ void mma_tf32(float* d, const uint32_t* a, const uint32_t* b) {
    asm volatile("mma.sync.aligned.m16n8k8.row.col.f32.tf32.tf32.f32 "
        "{%0,%1,%2,%3}, {%4,%5,%6,%7}, {%8,%9}, {%0,%1,%2,%3};"
        : "+f"(d[0]), "+f"(d[1]), "+f"(d[2]), "+f"(d[3])
        : "r"(a[0]), "r"(a[1]), "r"(a[2]), "r"(a[3]), "r"(b[0]), "r"(b[1]));
}

extern "C" __global__ void __launch_bounds__(THREADS, 1)
ts_fused_kernel(const float* __restrict__ x, const float* __restrict__ clusters,
                float* __restrict__ out) {
    extern __shared__ char smem[];
    const uint32_t sb = (uint32_t)__cvta_generic_to_shared(smem);

    const int tid  = threadIdx.x;
    const int lane = tid & 31;
    const int w    = tid >> 5;           // 0..15
    const int g    = lane >> 2;          // MMA groupID
    const int t4   = lane & 3;           // MMA threadID-in-group
    const int n0   = blockIdx.x * NROWS;
    const int f0   = 2 * w;              // warp owns f-planes f0, f0+1

    // ---- cp.async addressing: natural cells with fc^t XOR swizzle ------------
    // cell idx = tid + 512r : row = idx>>6, t = (idx>>3)&7, fc = idx&7
    const int t_ld  = (tid >> 3) & 7;
    const int fc_ld = tid & 7;
    const uint32_t cellp = (uint32_t)((tid & ~7) | ((tid ^ (tid >> 3)) & 7));  // swizzled
    const char* xsrc = (const char*)x
        + ((size_t)(n0 + (tid >> 6)) * T_DIM + t_ld) * 128 + (size_t)fc_ld * 16;
    const char* csrc = (const char*)clusters
        + ((size_t)(tid >> 6) * T_DIM + t_ld) * 128 + (size_t)fc_ld * 16;
    const uint32_t xdst = sb + OFF_XNAT + cellp * 16;
    const uint32_t cdst = sb + OFF_CNAT + cellp * 16;

    auto prefetch = [&](int ci) {
        if (ci >= NCH) return;
        const size_t tadv = (size_t)ci * TCH * 128;     // +1024B per chunk
        const uint32_t xo = (uint32_t)(ci & 1) * XNAT_SZ;
        const uint32_t co = (uint32_t)(ci & 1) * CNAT_SZ;
        #pragma unroll
        for (int r = 0; r < 2; r++)   // x: 1024 cells
            cp_async16(xdst + xo + (uint32_t)(r * 8192), xsrc + tadv + (size_t)r * 131072);
        #pragma unroll
        for (int r = 0; r < 4; r++)   // c: 2048 cells
            cp_async16(cdst + co + (uint32_t)(r * 8192), csrc + tadv + (size_t)r * 131072);
    };

    // ---- transpose task mapping ----------------------------------------------
    const int tf = tid & 31;             // f of transpose task
    const int tq = (tid >> 5) & 1;       // t-quad (t = 4q..4q+3)
    const int tn = tid >> 6;             // base row (+8r)

    float acc[2][4][4];
    #pragma unroll
    for (int fp = 0; fp < 2; fp++)
        #pragma unroll
        for (int nt = 0; nt < 4; nt++)
            #pragma unroll
            for (int e = 0; e < 4; e++) acc[fp][nt][e] = 0.f;
    float x2loc[2] = {0.f, 0.f};
    float c2loc[4] = {0.f, 0.f, 0.f, 0.f};

    prefetch(0); cp_commit();

    for (int ci = 0; ci < NCH; ci++) {
        prefetch(ci + 1); cp_commit();   // uniform group count (empty tail)
        cp_wait1();
        __syncthreads();                  // chunk ci visible; planes consumed

        const float* xn = (const float*)(smem + OFF_XNAT + (ci & 1) * XNAT_SZ);
        const float* cn = (const float*)(smem + OFF_CNAT + (ci & 1) * CNAT_SZ);
        uint32_t* A = (uint32_t*)(smem + OFF_APL);
        uint32_t* B = (uint32_t*)(smem + OFF_BPL);

        // ---- transpose + tf32 cvt: x -> A[f][n][t], accumulate x^2 ------------
        #pragma unroll
        for (int r = 0; r < 2; r++) {
            const int n = tn + 8 * r;
            uint32_t tv[4]; float s = x2loc[r];
            #pragma unroll
            for (int j = 0; j < 4; j++) {
                const int t = 4 * tq + j;
                float v = xn[((n * 8 + t) * 8 + ((tf >> 2) ^ t)) * 4 + (tf & 3)];
                tv[j] = cvt_tf32(v);
                s = fmaf(v, v, s);
            }
            x2loc[r] = s;
            *(uint4*)&A[tf * A_STRIDE + n * 8 + 4 * tq] =
                make_uint4(tv[0], tv[1], tv[2], tv[3]);
        }
        // ---- transpose + tf32 cvt: c -> B[f][k][t], accumulate c^2 ------------
        #pragma unroll
        for (int r = 0; r < 4; r++) {
            const int k = tn + 8 * r;
            uint32_t tv[4]; float s = c2loc[r];
            #pragma unroll
            for (int j = 0; j < 4; j++) {
                const int t = 4 * tq + j;
                float v = cn[((k * 8 + t) * 8 + ((tf >> 2) ^ t)) * 4 + (tf & 3)];
                tv[j] = cvt_tf32(v);
                s = fmaf(v, v, s);
            }
            c2loc[r] = s;
            *(uint4*)&B[tf * B_STRIDE + k * 8 + 4 * tq] =
                make_uint4(tv[0], tv[1], tv[2], tv[3]);
        }
        __syncthreads();                  // planes complete

        // ---- MMAs: warp's 2 f-planes x 4 k-clusters ---------------------------
        #pragma unroll
        for (int fp = 0; fp < 2; fp++) {
            const uint32_t* Af = (const uint32_t*)(smem + OFF_APL) + (f0 + fp) * A_STRIDE;
            const uint32_t* Bf = (const uint32_t*)(smem + OFF_BPL) + (f0 + fp) * B_STRIDE;
            uint32_t a[4];
            a[0] = Af[g * 8 + t4];        a[1] = Af[(g + 8) * 8 + t4];
            a[2] = Af[g * 8 + t4 + 4];    a[3] = Af[(g + 8) * 8 + t4 + 4];
            #pragma unroll
            for (int nt = 0; nt < 4; nt++) {
                uint32_t b[2];
                b[0] = Bf[(nt * 8 + g) * 8 + t4];
                b[1] = Bf[(nt * 8 + g) * 8 + t4 + 4];
                mma_tf32(acc[fp][nt], a, b);
            }
        }
        // next iteration's top barrier protects plane overwrite
    }
    __syncthreads();

    // ---- epilogue: reduce x2/c2 ----------------------------------------------
    float* x2red = (float*)(smem + OFF_X2RED);   // [q][n][f]
    float* c2red = (float*)(smem + OFF_C2RED);   // [q][k][f]
    float* x2s   = (float*)(smem + OFF_X2S);     // [n][f]
    float* c2s   = (float*)(smem + OFF_C2S);     // [k][f]
    float* epart = (float*)(smem + OFF_EPART);   // [w][n][k]

    #pragma unroll
    for (int r = 0; r < 2; r++)
        x2red[tq * 512 + (tn + 8 * r) * 32 + tf] = x2loc[r];
    #pragma unroll
    for (int r = 0; r < 4; r++)
        c2red[tq * 1024 + (tn + 8 * r) * 32 + tf] = c2loc[r];
    __syncthreads();

    x2s[tid] = x2red[tid] + x2red[tid + 512];
    #pragma unroll
    for (int e = 0; e < 2; e++) {
        int p = tid + 512 * e;
        c2s[p] = c2red[p] + c2red[p + 1024];
    }
    __syncthreads();

    // ---- sqrt + sum over this warp's 2 f's -> epart[w][n][k] ------------------
    #pragma unroll
    for (int nt = 0; nt < 4; nt++) {
        const int k0 = nt * 8 + 2 * t4, k1 = k0 + 1;
        float e00 = 0.f, e01 = 0.f, e10 = 0.f, e11 = 0.f;
        #pragma unroll
        for (int fp = 0; fp < 2; fp++) {
            const int f = f0 + fp;
            const float xa = x2s[g * 32 + f], xb = x2s[(g + 8) * 32 + f];
            const float ca = c2s[k0 * 32 + f], cb = c2s[k1 * 32 + f];
            e00 += fsqrt_approx(fmaxf(fmaf(-2.f, acc[fp][nt][0], xa + ca), 0.f));
            e01 += fsqrt_approx(fmaxf(fmaf(-2.f, acc[fp][nt][1], xa + cb), 0.f));
            e10 += fsqrt_approx(fmaxf(fmaf(-2.f, acc[fp][nt][2], xb + ca), 0.f));
            e11 += fsqrt_approx(fmaxf(fmaf(-2.f, acc[fp][nt][3], xb + cb), 0.f));
        }
        epart[w * 512 + g * 32 + k0]       = e00;
        epart[w * 512 + g * 32 + k1]       = e01;
        epart[w * 512 + (g + 8) * 32 + k0] = e10;
        epart[w * 512 + (g + 8) * 32 + k1] = e11;
    }
    __syncthreads();

    // ---- f-sum across warps + Student-t (warp w == n-row w) -------------------
    {
        float d = 0.f;
        #pragma unroll
        for (int ww = 0; ww < 16; ww++)
            d += epart[ww * 512 + tid];          // tid = w*32 + lane = n*32 + k
        float q = frcp_approx(fmaf(d, d, 1.0f)); // alpha = 1
        float s = q;
        #pragma unroll
        for (int off = 16; off > 0; off >>= 1)
            s += __shfl_xor_sync(0xffffffffu, s, off);
        out[(size_t)(n0 + w) * K_DIM + lane] = q * frcp_approx(s);
    }
}

extern "C" void kernel_launch(void* const* d_in, const int* in_sizes, int n_in,
                              void* d_out, int out_size) {
    const float* x        = (const float*)d_in[0];   // (2048, 128, 32)
    const float* clusters = (const float*)d_in[1];   // (32, 128, 32)
    float* out            = (float*)d_out;           // (2048, 32)
    (void)in_sizes; (void)n_in; (void)out_size;

    cudaFuncSetAttribute(ts_fused_kernel,
                         cudaFuncAttributeMaxDynamicSharedMemorySize, SMEM_TOTAL);
    ts_fused_kernel<<<NBLOCKS, THREADS, SMEM_TOTAL>>>(x, clusters, out);
}